// round 1
// baseline (speedup 1.0000x reference)
#include <cuda_runtime.h>
#include <cuda_bf16.h>
#include <cstdint>

#define HEADS 12
#define HEAD_S 64
#define BATCH 32
#define SEQ 512
#define DIM 768
#define NPROJ (HEADS * HEAD_S * 2)   // 1536
#define MROWS (BATCH * SEQ)          // 16384
#define NEGC 1000000000000.0f

// -------- scratch (device globals; no allocation allowed) --------
__device__ __nv_bfloat16 g_Wt[NPROJ * DIM];                    // [n][k] transposed bf16 W
__device__ __nv_bfloat16 g_Q[(size_t)BATCH * HEADS * SEQ * HEAD_S];
__device__ __nv_bfloat16 g_K[(size_t)BATCH * HEADS * SEQ * HEAD_S];
__device__ float g_sin[SEQ * 32];
__device__ float g_cos[SEQ * 32];

// -------- helpers --------
__device__ __forceinline__ uint32_t saddr(const void* p) {
    return (uint32_t)__cvta_generic_to_shared(p);
}
__device__ __forceinline__ unsigned pk(float a, float b) {
    __nv_bfloat162 h = __floats2bfloat162_rn(a, b);
    return *reinterpret_cast<unsigned*>(&h);
}
__device__ __forceinline__ void ldmx4(unsigned* r, uint32_t addr) {
    asm volatile("ldmatrix.sync.aligned.m8n8.x4.shared.b16 {%0,%1,%2,%3},[%4];"
                 : "=r"(r[0]), "=r"(r[1]), "=r"(r[2]), "=r"(r[3]) : "r"(addr));
}
__device__ __forceinline__ void mma16816(float* c, const unsigned* a, const unsigned* b) {
    asm volatile(
        "mma.sync.aligned.m16n8k16.row.col.f32.bf16.bf16.f32 "
        "{%0,%1,%2,%3},{%4,%5,%6,%7},{%8,%9},{%0,%1,%2,%3};"
        : "+f"(c[0]), "+f"(c[1]), "+f"(c[2]), "+f"(c[3])
        : "r"(a[0]), "r"(a[1]), "r"(a[2]), "r"(a[3]), "r"(b[0]), "r"(b[1]));
}

// -------- prep: transpose W (f32 [k][n]) -> Wt (bf16 [n][k]) --------
__global__ void prep_wt(const float* __restrict__ W) {
    __shared__ float t[32][33];
    int kt = blockIdx.y * 32, nt = blockIdx.x * 32;
    int tx = threadIdx.x, ty = threadIdx.y;    // block (32,8)
    for (int i = ty; i < 32; i += 8)
        t[i][tx] = W[(size_t)(kt + i) * NPROJ + nt + tx];
    __syncthreads();
    for (int i = ty; i < 32; i += 8)
        g_Wt[(size_t)(nt + i) * DIM + kt + tx] = __float2bfloat16(t[tx][i]);
}

// -------- prep: rope table --------
__global__ void prep_rope() {
    int idx = blockIdx.x * blockDim.x + threadIdx.x;
    if (idx < SEQ * 32) {
        int l = idx / 32, i = idx % 32;
        float freq = powf(10000.0f, -(2.0f * (float)i) / 64.0f);
        float ang = (float)l * freq;
        g_sin[idx] = sinf(ang);
        g_cos[idx] = cosf(ang);
    }
}

// =============================================================
// Stage 1: proj = x @ W + b, apply RoPE, write Q/K bf16
// block tile 128(m) x 128(n), BK=64, 8 warps (4x2), warp tile 32x64
// grid: (128 mtiles, 12 heads)
// =============================================================
__global__ __launch_bounds__(256) void stage1(const float* __restrict__ x,
                                              const float* __restrict__ bias) {
    __shared__ __nv_bfloat16 sA[128 * 72];
    __shared__ __nv_bfloat16 sB[128 * 72];

    int mblk = blockIdx.x;
    int head = blockIdx.y;
    int tid = threadIdx.x, warp = tid >> 5, lane = tid & 31;
    int wm = (warp >> 1) * 32;   // warp m offset
    int wn = (warp & 1) * 64;    // warp n offset

    float acc[2][8][4];
#pragma unroll
    for (int a = 0; a < 2; a++)
#pragma unroll
        for (int b = 0; b < 8; b++)
#pragma unroll
            for (int c = 0; c < 4; c++) acc[a][b][c] = 0.0f;

    const float* xblk = x + (size_t)mblk * 128 * DIM;
    const __nv_bfloat16* wblk = g_Wt + (size_t)head * 128 * DIM;

    for (int kt = 0; kt < DIM; kt += 64) {
        // load A: 128 rows x 64 fp32 -> bf16. 8 threads/row, 8 floats each.
#pragma unroll
        for (int it = 0; it < 4; it++) {
            int row = it * 32 + (tid >> 3);
            int kk = (tid & 7) * 8;
            const float4* p = (const float4*)(xblk + (size_t)row * DIM + kt + kk);
            float4 u = p[0], v = p[1];
            uint4 w;
            w.x = pk(u.x, u.y); w.y = pk(u.z, u.w);
            w.z = pk(v.x, v.y); w.w = pk(v.z, v.w);
            *(uint4*)&sA[row * 72 + kk] = w;
        }
        // load B: Wt rows n (within head block), cols k
#pragma unroll
        for (int it = 0; it < 4; it++) {
            int row = it * 32 + (tid >> 3);
            int kk = (tid & 7) * 8;
            uint4 w = *(const uint4*)(wblk + (size_t)row * DIM + kt + kk);
            *(uint4*)&sB[row * 72 + kk] = w;
        }
        __syncthreads();

#pragma unroll
        for (int ks = 0; ks < 4; ks++) {
            int kb = ks * 16;
            unsigned a[2][4], bf[4][4];
#pragma unroll
            for (int mt = 0; mt < 2; mt++) {
                int r = wm + mt * 16 + (lane & 7) + ((lane >> 3) & 1) * 8;
                int c = kb + (lane >> 4) * 8;
                ldmx4(a[mt], saddr(&sA[r * 72 + c]));
            }
#pragma unroll
            for (int np = 0; np < 4; np++) {
                int g = lane >> 3;
                int r = wn + np * 16 + (lane & 7) + (g >> 1) * 8;
                int c = kb + (g & 1) * 8;
                ldmx4(bf[np], saddr(&sB[r * 72 + c]));
            }
#pragma unroll
            for (int mt = 0; mt < 2; mt++)
#pragma unroll
                for (int np = 0; np < 4; np++) {
                    mma16816(acc[mt][2 * np], a[mt], &bf[np][0]);
                    mma16816(acc[mt][2 * np + 1], a[mt], &bf[np][2]);
                }
        }
        __syncthreads();
    }

    // epilogue: bias + RoPE, write Q/K bf16
    int gmb = mblk * 128;
#pragma unroll
    for (int mt = 0; mt < 2; mt++) {
#pragma unroll
        for (int nt = 0; nt < 8; nt++) {
            int ncol = wn + nt * 8 + 2 * (lane & 3);   // even, [0,128)
            int rch = ncol & 63;
            int i = rch >> 1;
            bool isQ = ncol < 64;
            int ngl = head * 128 + ncol;
            float b0 = bias[ngl], b1 = bias[ngl + 1];
#pragma unroll
            for (int rr = 0; rr < 2; rr++) {
                int row = wm + mt * 16 + (lane >> 2) + rr * 8;
                int gm = gmb + row;
                int bb = gm >> 9;
                int l = gm & 511;
                float v0 = acc[mt][nt][rr * 2 + 0] + b0;
                float v1 = acc[mt][nt][rr * 2 + 1] + b1;
                float sn = g_sin[l * 32 + i], cs = g_cos[l * 32 + i];
                float o0 = v0 * cs - v1 * sn;
                float o1 = v1 * cs + v0 * sn;
                size_t off = (((size_t)(bb * HEADS + head) * SEQ + l) * HEAD_S + rch);
                __nv_bfloat16* dst = (isQ ? g_Q : g_K) + off;
                *(__nv_bfloat162*)dst = __floats2bfloat162_rn(o0, o1);
            }
        }
    }
}

// =============================================================
// Stage 2: per (b,h): S = Q @ K^T, mask + tril + scale, write fp32
// block tile 128x128, grid (4 ntiles, 4 mtiles, 384 bh)
// =============================================================
__global__ __launch_bounds__(256) void stage2(const float* __restrict__ mask,
                                              float* __restrict__ out) {
    __shared__ __nv_bfloat16 sQ[128 * 72];
    __shared__ __nv_bfloat16 sK[128 * 72];

    int ntb = blockIdx.x, mtb = blockIdx.y, bh = blockIdx.z;
    int b = bh / HEADS;
    int tid = threadIdx.x, warp = tid >> 5, lane = tid & 31;
    int wm = (warp >> 1) * 32;
    int wn = (warp & 1) * 64;

    const __nv_bfloat16* Qb = g_Q + (size_t)bh * SEQ * HEAD_S + (size_t)mtb * 128 * HEAD_S;
    const __nv_bfloat16* Kb = g_K + (size_t)bh * SEQ * HEAD_S + (size_t)ntb * 128 * HEAD_S;

    // load tiles: 128 rows x 64 bf16, 8 threads/row (uint4)
#pragma unroll
    for (int it = 0; it < 4; it++) {
        int row = it * 32 + (tid >> 3);
        int kk = (tid & 7) * 8;
        *(uint4*)&sQ[row * 72 + kk] = *(const uint4*)(Qb + (size_t)row * HEAD_S + kk);
        *(uint4*)&sK[row * 72 + kk] = *(const uint4*)(Kb + (size_t)row * HEAD_S + kk);
    }
    __syncthreads();

    float acc[2][8][4];
#pragma unroll
    for (int a = 0; a < 2; a++)
#pragma unroll
        for (int c = 0; c < 8; c++)
#pragma unroll
            for (int d = 0; d < 4; d++) acc[a][c][d] = 0.0f;

#pragma unroll
    for (int ks = 0; ks < 4; ks++) {
        int kb = ks * 16;
        unsigned a[2][4], bf[4][4];
#pragma unroll
        for (int mt = 0; mt < 2; mt++) {
            int r = wm + mt * 16 + (lane & 7) + ((lane >> 3) & 1) * 8;
            int c = kb + (lane >> 4) * 8;
            ldmx4(a[mt], saddr(&sQ[r * 72 + c]));
        }
#pragma unroll
        for (int np = 0; np < 4; np++) {
            int g = lane >> 3;
            int r = wn + np * 16 + (lane & 7) + (g >> 1) * 8;
            int c = kb + (g & 1) * 8;
            ldmx4(bf[np], saddr(&sK[r * 72 + c]));
        }
#pragma unroll
        for (int mt = 0; mt < 2; mt++)
#pragma unroll
            for (int np = 0; np < 4; np++) {
                mma16816(acc[mt][2 * np], a[mt], &bf[np][0]);
                mma16816(acc[mt][2 * np + 1], a[mt], &bf[np][2]);
            }
    }

    // epilogue: mask (row & col), causal tril, scale 1/8
    float* ob = out + (size_t)bh * (SEQ * SEQ);
    const float* mrow = mask + (size_t)b * SEQ;
#pragma unroll
    for (int mt = 0; mt < 2; mt++) {
#pragma unroll
        for (int rr = 0; rr < 2; rr++) {
            int row = mtb * 128 + wm + mt * 16 + (lane >> 2) + rr * 8;
            float m2 = __ldg(&mrow[row]);
#pragma unroll
            for (int nt = 0; nt < 8; nt++) {
                int col = ntb * 128 + wn + nt * 8 + 2 * (lane & 3);
                float v0 = acc[mt][nt][rr * 2 + 0];
                float v1 = acc[mt][nt][rr * 2 + 1];
                float m3a = __ldg(&mrow[col]);
                float m3b = __ldg(&mrow[col + 1]);
                v0 = v0 * m2 + (1.0f - m2) * (-NEGC);
                v1 = v1 * m2 + (1.0f - m2) * (-NEGC);
                v0 = v0 * m3a + (1.0f - m3a) * (-NEGC);
                v1 = v1 * m3b + (1.0f - m3b) * (-NEGC);
                if (row > col)     v0 -= NEGC;
                if (row > col + 1) v1 -= NEGC;
                v0 *= 0.125f;
                v1 *= 0.125f;
                float2 w = make_float2(v0, v1);
                *(float2*)&ob[(size_t)row * SEQ + col] = w;
            }
        }
    }
}

extern "C" void kernel_launch(void* const* d_in, const int* in_sizes, int n_in,
                              void* d_out, int out_size) {
    const float* x    = (const float*)d_in[0];
    const float* mask = (const float*)d_in[1];
    const float* W    = (const float*)d_in[2];
    const float* bias = (const float*)d_in[3];
    float* out = (float*)d_out;

    prep_wt<<<dim3(NPROJ / 32, DIM / 32), dim3(32, 8)>>>(W);
    prep_rope<<<(SEQ * 32 + 255) / 256, 256>>>();
    stage1<<<dim3(MROWS / 128, HEADS), 256>>>(x, bias);
    stage2<<<dim3(4, 4, BATCH * HEADS), 256>>>(mask, out);
}

// round 2
// speedup vs baseline: 1.0962x; 1.0962x over previous
#include <cuda_runtime.h>
#include <cuda_bf16.h>
#include <cstdint>

#define HEADS 12
#define HEAD_S 64
#define BATCH 32
#define SEQ 512
#define DIM 768
#define NPROJ (HEADS * HEAD_S * 2)   // 1536
#define MROWS (BATCH * SEQ)          // 16384
#define NEGC 1000000000000.0f
#define NEG8 (NEGC * 0.125f)

// -------- scratch (device globals; no allocation allowed) --------
__device__ __nv_bfloat16 g_x[(size_t)MROWS * DIM];             // bf16 copy of x
__device__ __nv_bfloat16 g_Wt[NPROJ * DIM];                    // [n][k] transposed bf16 W
__device__ __nv_bfloat16 g_Q[(size_t)BATCH * HEADS * SEQ * HEAD_S];
__device__ __nv_bfloat16 g_K[(size_t)BATCH * HEADS * SEQ * HEAD_S];
__device__ float g_sin[SEQ * 32];
__device__ float g_cos[SEQ * 32];

// -------- helpers --------
__device__ __forceinline__ uint32_t saddr(const void* p) {
    return (uint32_t)__cvta_generic_to_shared(p);
}
__device__ __forceinline__ unsigned pk(float a, float b) {
    __nv_bfloat162 h = __floats2bfloat162_rn(a, b);
    return *reinterpret_cast<unsigned*>(&h);
}
__device__ __forceinline__ void cpasync16(void* smem, const void* gmem) {
    uint32_t s = saddr(smem);
    asm volatile("cp.async.cg.shared.global [%0], [%1], 16;" :: "r"(s), "l"(gmem));
}
#define CP_COMMIT asm volatile("cp.async.commit_group;")
#define CP_WAIT(n) asm volatile("cp.async.wait_group %0;" :: "n"(n))

__device__ __forceinline__ void ldmx4(unsigned* r, uint32_t addr) {
    asm volatile("ldmatrix.sync.aligned.m8n8.x4.shared.b16 {%0,%1,%2,%3},[%4];"
                 : "=r"(r[0]), "=r"(r[1]), "=r"(r[2]), "=r"(r[3]) : "r"(addr));
}
__device__ __forceinline__ void mma16816(float* c, const unsigned* a, const unsigned* b) {
    asm volatile(
        "mma.sync.aligned.m16n8k16.row.col.f32.bf16.bf16.f32 "
        "{%0,%1,%2,%3},{%4,%5,%6,%7},{%8,%9},{%0,%1,%2,%3};"
        : "+f"(c[0]), "+f"(c[1]), "+f"(c[2]), "+f"(c[3])
        : "r"(a[0]), "r"(a[1]), "r"(a[2]), "r"(a[3]), "r"(b[0]), "r"(b[1]));
}

// =============================================================
// Fused prep: x->bf16 (blocks 0..6143), W transpose (6144..7295),
//             rope table (7296..7359)
// =============================================================
#define PREP_XBLK 6144
#define PREP_WBLK 1152
#define PREP_RBLK 64
__global__ __launch_bounds__(256) void prep(const float* __restrict__ x,
                                            const float* __restrict__ W) {
    __shared__ float t[32][33];
    int bid = blockIdx.x, tid = threadIdx.x;
    if (bid < PREP_XBLK) {
        size_t i = ((size_t)bid * 256 + tid) * 8;
        const float4* p = (const float4*)(x + i);
        float4 u = p[0], v = p[1];
        uint4 w;
        w.x = pk(u.x, u.y); w.y = pk(u.z, u.w);
        w.z = pk(v.x, v.y); w.w = pk(v.z, v.w);
        *(uint4*)&g_x[i] = w;
    } else if (bid < PREP_XBLK + PREP_WBLK) {
        int tile = bid - PREP_XBLK;
        int nt = (tile % 48) * 32, kt = (tile / 48) * 32;
        int tx = tid & 31, ty = tid >> 5;
        for (int i2 = ty; i2 < 32; i2 += 8)
            t[i2][tx] = W[(size_t)(kt + i2) * NPROJ + nt + tx];
        __syncthreads();
        for (int i2 = ty; i2 < 32; i2 += 8)
            g_Wt[(size_t)(nt + i2) * DIM + kt + tx] = __float2bfloat16(t[tx][i2]);
    } else {
        int idx = (bid - PREP_XBLK - PREP_WBLK) * 256 + tid;  // < 16384
        int l = idx >> 5, i2 = idx & 31;
        float freq = powf(10000.0f, -(2.0f * (float)i2) / 64.0f);
        float ang = (float)l * freq;
        g_sin[idx] = sinf(ang);
        g_cos[idx] = cosf(ang);
    }
}

// =============================================================
// Stage 1: proj = x @ W + b, RoPE, write Q/K bf16
// tile 128x128, BK=64, 2-stage cp.async pipeline, 8 warps
// dynamic smem: 2*(128*72 A + 128*72 B) bf16 = 73728 B
// =============================================================
#define ABUF (128 * 72)
#define S1_SMEM (4 * ABUF * 2)   // bytes

__global__ __launch_bounds__(256) void stage1(const float* __restrict__ bias) {
    extern __shared__ __nv_bfloat16 sm[];
    __nv_bfloat16* sA = sm;
    __nv_bfloat16* sB = sm + 2 * ABUF;

    int mblk = blockIdx.x;
    int head = blockIdx.y;
    int tid = threadIdx.x, warp = tid >> 5, lane = tid & 31;
    int wm = (warp >> 1) * 32;
    int wn = (warp & 1) * 64;

    const __nv_bfloat16* xb = g_x + (size_t)mblk * 128 * DIM;
    const __nv_bfloat16* wb = g_Wt + (size_t)head * 128 * DIM;

    int lrow = tid >> 3, lkk = (tid & 7) * 8;

    auto issue = [&](int st, int kt) {
#pragma unroll
        for (int it = 0; it < 4; it++) {
            int row = it * 32 + lrow;
            cpasync16(&sA[st * ABUF + row * 72 + lkk], xb + (size_t)row * DIM + kt + lkk);
            cpasync16(&sB[st * ABUF + row * 72 + lkk], wb + (size_t)row * DIM + kt + lkk);
        }
        CP_COMMIT;
    };

    float acc[2][8][4];
#pragma unroll
    for (int a = 0; a < 2; a++)
#pragma unroll
        for (int b = 0; b < 8; b++)
#pragma unroll
            for (int c = 0; c < 4; c++) acc[a][b][c] = 0.0f;

    issue(0, 0);
    issue(1, 64);

    const int NK = DIM / 64;   // 12
    for (int i = 0; i < NK; i++) {
        if (i == NK - 1) { CP_WAIT(0); } else { CP_WAIT(1); }
        __syncthreads();
        const __nv_bfloat16* cA = sA + (i & 1) * ABUF;
        const __nv_bfloat16* cB = sB + (i & 1) * ABUF;
#pragma unroll
        for (int ks = 0; ks < 4; ks++) {
            int kb = ks * 16;
            unsigned a[2][4], bf[4][4];
#pragma unroll
            for (int mt = 0; mt < 2; mt++) {
                int r = wm + mt * 16 + (lane & 7) + ((lane >> 3) & 1) * 8;
                int c = kb + (lane >> 4) * 8;
                ldmx4(a[mt], saddr(&cA[r * 72 + c]));
            }
#pragma unroll
            for (int np = 0; np < 4; np++) {
                int g = lane >> 3;
                int r = wn + np * 16 + (lane & 7) + (g >> 1) * 8;
                int c = kb + (g & 1) * 8;
                ldmx4(bf[np], saddr(&cB[r * 72 + c]));
            }
#pragma unroll
            for (int mt = 0; mt < 2; mt++)
#pragma unroll
                for (int np = 0; np < 4; np++) {
                    mma16816(acc[mt][2 * np], a[mt], &bf[np][0]);
                    mma16816(acc[mt][2 * np + 1], a[mt], &bf[np][2]);
                }
        }
        __syncthreads();
        if (i + 2 < NK) issue(i & 1, (i + 2) * 64);
    }

    // epilogue: bias + RoPE, write Q/K bf16
    int gmb = mblk * 128;
#pragma unroll
    for (int mt = 0; mt < 2; mt++) {
#pragma unroll
        for (int nt = 0; nt < 8; nt++) {
            int ncol = wn + nt * 8 + 2 * (lane & 3);   // even, [0,128)
            int rch = ncol & 63;
            int i = rch >> 1;
            bool isQ = ncol < 64;
            int ngl = head * 128 + ncol;
            float b0 = bias[ngl], b1 = bias[ngl + 1];
#pragma unroll
            for (int rr = 0; rr < 2; rr++) {
                int row = wm + mt * 16 + (lane >> 2) + rr * 8;
                int gm = gmb + row;
                int bb = gm >> 9;
                int l = gm & 511;
                float v0 = acc[mt][nt][rr * 2 + 0] + b0;
                float v1 = acc[mt][nt][rr * 2 + 1] + b1;
                float sn = g_sin[l * 32 + i], cs = g_cos[l * 32 + i];
                float o0 = v0 * cs - v1 * sn;
                float o1 = v1 * cs + v0 * sn;
                size_t off = (((size_t)(bb * HEADS + head) * SEQ + l) * HEAD_S + rch);
                __nv_bfloat16* dst = (isQ ? g_Q : g_K) + off;
                *(__nv_bfloat162*)dst = __floats2bfloat162_rn(o0, o1);
            }
        }
    }
}

// =============================================================
// Stage 2: per (b,h): S = Q @ K^T, mask + tril + scale, fp32 out
// block tile 128x128, grid (4 ntiles, 4 mtiles, 384 bh)
// =============================================================
__global__ __launch_bounds__(256) void stage2(const float* __restrict__ mask,
                                              float* __restrict__ out) {
    __shared__ __nv_bfloat16 sQ[128 * 72];
    __shared__ __nv_bfloat16 sK[128 * 72];
    __shared__ float s_rs[128], s_ra[128], s_cm[128], s_ca[128];

    int ntb = blockIdx.x, mtb = blockIdx.y, bh = blockIdx.z;
    int b = bh / HEADS;
    int tid = threadIdx.x, warp = tid >> 5, lane = tid & 31;
    int wm = (warp >> 1) * 32;
    int wn = (warp & 1) * 64;

    const __nv_bfloat16* Qb = g_Q + (size_t)bh * SEQ * HEAD_S + (size_t)mtb * 128 * HEAD_S;
    const __nv_bfloat16* Kb = g_K + (size_t)bh * SEQ * HEAD_S + (size_t)ntb * 128 * HEAD_S;

    // async tile loads: 128 rows x 64 bf16, 8 threads/row
    int lrow = tid >> 3, lkk = (tid & 7) * 8;
#pragma unroll
    for (int it = 0; it < 4; it++) {
        int row = it * 32 + lrow;
        cpasync16(&sQ[row * 72 + lkk], Qb + (size_t)row * HEAD_S + lkk);
        cpasync16(&sK[row * 72 + lkk], Kb + (size_t)row * HEAD_S + lkk);
    }
    CP_COMMIT;

    // mask precompute overlapped with loads
    if (tid < 128) {
        float m2 = mask[(size_t)b * SEQ + mtb * 128 + tid];
        s_rs[tid] = m2 * 0.125f;
        s_ra[tid] = (1.0f - m2) * (-NEG8);
        float m3 = mask[(size_t)b * SEQ + ntb * 128 + tid];
        s_cm[tid] = m3;
        s_ca[tid] = (1.0f - m3) * (-NEG8);
    }
    CP_WAIT(0);
    __syncthreads();

    float acc[2][8][4];
#pragma unroll
    for (int a = 0; a < 2; a++)
#pragma unroll
        for (int c = 0; c < 8; c++)
#pragma unroll
            for (int d = 0; d < 4; d++) acc[a][c][d] = 0.0f;

#pragma unroll
    for (int ks = 0; ks < 4; ks++) {
        int kb = ks * 16;
        unsigned a[2][4], bf[4][4];
#pragma unroll
        for (int mt = 0; mt < 2; mt++) {
            int r = wm + mt * 16 + (lane & 7) + ((lane >> 3) & 1) * 8;
            int c = kb + (lane >> 4) * 8;
            ldmx4(a[mt], saddr(&sQ[r * 72 + c]));
        }
#pragma unroll
        for (int np = 0; np < 4; np++) {
            int g = lane >> 3;
            int r = wn + np * 16 + (lane & 7) + (g >> 1) * 8;
            int c = kb + (g & 1) * 8;
            ldmx4(bf[np], saddr(&sK[r * 72 + c]));
        }
#pragma unroll
        for (int mt = 0; mt < 2; mt++)
#pragma unroll
            for (int np = 0; np < 4; np++) {
                mma16816(acc[mt][2 * np], a[mt], &bf[np][0]);
                mma16816(acc[mt][2 * np + 1], a[mt], &bf[np][2]);
            }
    }

    // epilogue: v = (S*rs + ra)*cm + ca - (row>col)*NEG/8 ; streaming stores
    float* ob = out + (size_t)bh * (SEQ * SEQ);
#pragma unroll
    for (int mt = 0; mt < 2; mt++) {
#pragma unroll
        for (int rr = 0; rr < 2; rr++) {
            int rl = wm + mt * 16 + (lane >> 2) + rr * 8;
            int row = mtb * 128 + rl;
            float rs = s_rs[rl], ra = s_ra[rl];
#pragma unroll
            for (int nt = 0; nt < 8; nt++) {
                int cl = wn + nt * 8 + 2 * (lane & 3);
                int col = ntb * 128 + cl;
                float v0 = (acc[mt][nt][rr * 2 + 0] * rs + ra) * s_cm[cl] + s_ca[cl];
                float v1 = (acc[mt][nt][rr * 2 + 1] * rs + ra) * s_cm[cl + 1] + s_ca[cl + 1];
                if (row > col)     v0 -= NEG8;
                if (row > col + 1) v1 -= NEG8;
                __stcs((float2*)&ob[(size_t)row * SEQ + col], make_float2(v0, v1));
            }
        }
    }
}

extern "C" void kernel_launch(void* const* d_in, const int* in_sizes, int n_in,
                              void* d_out, int out_size) {
    const float* x    = (const float*)d_in[0];
    const float* mask = (const float*)d_in[1];
    const float* W    = (const float*)d_in[2];
    const float* bias = (const float*)d_in[3];
    float* out = (float*)d_out;

    static bool attr_done = false;
    if (!attr_done) {
        cudaFuncSetAttribute(stage1, cudaFuncAttributeMaxDynamicSharedMemorySize, S1_SMEM);
        attr_done = true;
    }

    prep<<<PREP_XBLK + PREP_WBLK + PREP_RBLK, 256>>>(x, W);
    stage1<<<dim3(MROWS / 128, HEADS), 256, S1_SMEM>>>(bias);
    stage2<<<dim3(4, 4, BATCH * HEADS), 256>>>(mask, out);
}